// round 1
// baseline (speedup 1.0000x reference)
#include <cuda_runtime.h>
#include <cstdint>
#include <cstddef>

// ---------------------------------------------------------------------------
// DynamicGIN on GB300 — round 1 baseline
// Pipeline:
//  zero aggA -> scatter0 -> GEMM(x+aggA @ w1_0, relu) -> GEMM(@ w2_0) -> LN+relu (h0)
//  zero aggA -> scatter1 -> GEMM(h0+aggA @ w1_1, relu) -> GEMM(@ w2_1) -> LN+relu (h1)
//  GEMM(h1 @ gate_w1, relu) -> gate dot -> segmax -> exp/segsum -> pooled -> classifier
// ---------------------------------------------------------------------------

#define NMAX 100000
#define GMAXC 1024

__device__ float g_bufA[(size_t)NMAX * 256]; // agg scratch, later h1
__device__ float g_bufB[(size_t)NMAX * 256]; // MLP mid scratch
__device__ float g_bufC[(size_t)NMAX * 256]; // h0
__device__ float g_gate[NMAX];
__device__ float g_exp[NMAX];
__device__ unsigned g_gmax[GMAXC];
__device__ float g_den[GMAXC];
__device__ float g_pooled[GMAXC * 256];

static inline int cdiv(int a, int b) { return (a + b - 1) / b; }

// ---------------------------- zero kernels ---------------------------------
__global__ void k_zero4(float4* __restrict__ p, int n4) {
    int i = blockIdx.x * blockDim.x + threadIdx.x;
    if (i < n4) p[i] = make_float4(0.f, 0.f, 0.f, 0.f);
}

__global__ void k_zero_small(unsigned* __restrict__ gmax, float* __restrict__ den,
                             float* __restrict__ pooled, int G) {
    int i = blockIdx.x * blockDim.x + threadIdx.x;
    if (i < G) { gmax[i] = 0u; den[i] = 0.f; }
    if (i < G * 256) pooled[i] = 0.f;
}

// ---------------------------- edge scatter ---------------------------------
__device__ __forceinline__ void red_add_v4(float* addr, float4 v) {
    asm volatile("red.global.add.v4.f32 [%0], {%1,%2,%3,%4};"
                 :: "l"(addr), "f"(v.x), "f"(v.y), "f"(v.z), "f"(v.w)
                 : "memory");
}

template <int F>
__global__ void k_scatter(const float* __restrict__ x, const int* __restrict__ src,
                          const int* __restrict__ dst, float* __restrict__ agg, int E) {
    int gid = blockIdx.x * blockDim.x + threadIdx.x;
    int e = gid >> 5;
    int lane = gid & 31;
    if (e >= E) return;
    int s = __ldg(&src[e]);
    int d = __ldg(&dst[e]);
    const float4* xs = (const float4*)(x + (size_t)s * F);
    float* ag = agg + (size_t)d * F;
#pragma unroll
    for (int i = 0; i < F / 128; i++) {
        int q = lane + i * 32;           // float4 index within row
        float4 v = __ldg(&xs[q]);
        red_add_v4(ag + q * 4, v);
    }
}

// ---------------------------- fp32 SGEMM -----------------------------------
// C[M,N] = epilogue( (A (+A2)) @ W + bias )
// Block tile 128x128, BK=16, 256 threads, 8x8 per-thread microtile.
template <bool ADD2, bool RELU>
__global__ void __launch_bounds__(256)
k_gemm(const float* __restrict__ A, const float* __restrict__ A2,
       const float* __restrict__ W, const float* __restrict__ bias,
       float* __restrict__ C, int M, int K, int N) {
    __shared__ float As[16][132]; // transposed: As[k][m], pad keeps 16B align
    __shared__ float Bs[16][132];

    const int tid = threadIdx.x;
    const int trow = tid >> 4;   // 0..15
    const int tcol = tid & 15;   // 0..15
    const int row0 = blockIdx.y * 128;
    const int col0 = blockIdx.x * 128;

    float acc[8][8];
#pragma unroll
    for (int i = 0; i < 8; i++)
#pragma unroll
        for (int j = 0; j < 8; j++) acc[i][j] = 0.f;

    for (int k0 = 0; k0 < K; k0 += 16) {
        // A tile: 128 rows x 16 cols -> transposed store
#pragma unroll
        for (int t = 0; t < 2; t++) {
            int idx = tid + t * 256;       // float4 id 0..511
            int r = idx >> 2;              // 0..127
            int c = (idx & 3) * 4;         // 0,4,8,12
            int gr = row0 + r;
            float4 v = make_float4(0.f, 0.f, 0.f, 0.f);
            if (gr < M) {
                v = *(const float4*)(A + (size_t)gr * K + k0 + c);
                if (ADD2) {
                    float4 w = *(const float4*)(A2 + (size_t)gr * K + k0 + c);
                    v.x += w.x; v.y += w.y; v.z += w.z; v.w += w.w;
                }
            }
            As[c + 0][r] = v.x;
            As[c + 1][r] = v.y;
            As[c + 2][r] = v.z;
            As[c + 3][r] = v.w;
        }
        // B tile: 16 rows x 128 cols
#pragma unroll
        for (int t = 0; t < 2; t++) {
            int idx = tid + t * 256;
            int r = idx >> 5;              // 0..15
            int c = (idx & 31) * 4;        // 0..124
            float4 v = *(const float4*)(W + (size_t)(k0 + r) * N + col0 + c);
            *(float4*)&Bs[r][c] = v;
        }
        __syncthreads();

#pragma unroll
        for (int k = 0; k < 16; k++) {
            float a[8], b[8];
            *(float4*)&a[0] = *(const float4*)&As[k][trow * 8];
            *(float4*)&a[4] = *(const float4*)&As[k][trow * 8 + 4];
            *(float4*)&b[0] = *(const float4*)&Bs[k][tcol * 8];
            *(float4*)&b[4] = *(const float4*)&Bs[k][tcol * 8 + 4];
#pragma unroll
            for (int i = 0; i < 8; i++)
#pragma unroll
                for (int j = 0; j < 8; j++) acc[i][j] += a[i] * b[j];
        }
        __syncthreads();
    }

#pragma unroll
    for (int i = 0; i < 8; i++) {
        int gr = row0 + trow * 8 + i;
        if (gr < M) {
#pragma unroll
            for (int j = 0; j < 8; j += 4) {
                int gc = col0 + tcol * 8 + j;
                float4 v;
                v.x = acc[i][j + 0] + __ldg(&bias[gc + 0]);
                v.y = acc[i][j + 1] + __ldg(&bias[gc + 1]);
                v.z = acc[i][j + 2] + __ldg(&bias[gc + 2]);
                v.w = acc[i][j + 3] + __ldg(&bias[gc + 3]);
                if (RELU) {
                    v.x = fmaxf(v.x, 0.f); v.y = fmaxf(v.y, 0.f);
                    v.z = fmaxf(v.z, 0.f); v.w = fmaxf(v.w, 0.f);
                }
                *(float4*)(C + (size_t)gr * N + gc) = v;
            }
        }
    }
}

// ---------------------------- LayerNorm + ReLU (in place, 256 cols) --------
__global__ void k_ln(float* __restrict__ h, const float* __restrict__ gamma,
                     const float* __restrict__ beta, int M) {
    int row = blockIdx.x * 8 + (threadIdx.x >> 5);
    int lane = threadIdx.x & 31;
    if (row >= M) return;
    float4* p = (float4*)(h + (size_t)row * 256);
    float4 v0 = p[lane];
    float4 v1 = p[lane + 32];
    float s = v0.x + v0.y + v0.z + v0.w + v1.x + v1.y + v1.z + v1.w;
    float ss = v0.x * v0.x + v0.y * v0.y + v0.z * v0.z + v0.w * v0.w
             + v1.x * v1.x + v1.y * v1.y + v1.z * v1.z + v1.w * v1.w;
#pragma unroll
    for (int off = 16; off > 0; off >>= 1) {
        s  += __shfl_xor_sync(0xffffffffu, s, off);
        ss += __shfl_xor_sync(0xffffffffu, ss, off);
    }
    float mean = s * (1.f / 256.f);
    float var  = ss * (1.f / 256.f) - mean * mean;
    float inv  = rsqrtf(var + 1e-5f);
    const float4* g4 = (const float4*)gamma;
    const float4* b4 = (const float4*)beta;
    float4 g0 = __ldg(&g4[lane]),      b0 = __ldg(&b4[lane]);
    float4 g1 = __ldg(&g4[lane + 32]), b1 = __ldg(&b4[lane + 32]);
    float4 o0, o1;
    o0.x = fmaxf((v0.x - mean) * inv * g0.x + b0.x, 0.f);
    o0.y = fmaxf((v0.y - mean) * inv * g0.y + b0.y, 0.f);
    o0.z = fmaxf((v0.z - mean) * inv * g0.z + b0.z, 0.f);
    o0.w = fmaxf((v0.w - mean) * inv * g0.w + b0.w, 0.f);
    o1.x = fmaxf((v1.x - mean) * inv * g1.x + b1.x, 0.f);
    o1.y = fmaxf((v1.y - mean) * inv * g1.y + b1.y, 0.f);
    o1.z = fmaxf((v1.z - mean) * inv * g1.z + b1.z, 0.f);
    o1.w = fmaxf((v1.w - mean) * inv * g1.w + b1.w, 0.f);
    p[lane] = o0;
    p[lane + 32] = o1;
}

// ---------------------------- gate second layer (128 -> 1) -----------------
__global__ void k_gatedot(const float* __restrict__ t, const float* __restrict__ w2,
                          const float* __restrict__ b2, float* __restrict__ gate, int M) {
    int row = blockIdx.x * 8 + (threadIdx.x >> 5);
    int lane = threadIdx.x & 31;
    if (row >= M) return;
    float4 v = __ldg(&((const float4*)(t + (size_t)row * 128))[lane]);
    float4 w = __ldg(&((const float4*)w2)[lane]);
    float s = v.x * w.x + v.y * w.y + v.z * w.z + v.w * w.w;
#pragma unroll
    for (int off = 16; off > 0; off >>= 1)
        s += __shfl_xor_sync(0xffffffffu, s, off);
    if (lane == 0) gate[row] = s + __ldg(&b2[0]);
}

// ---------------------------- segment softmax + pool ------------------------
__device__ __forceinline__ unsigned enc_ord(float f) {
    unsigned u = __float_as_uint(f);
    return (u & 0x80000000u) ? ~u : (u | 0x80000000u);
}
__device__ __forceinline__ float dec_ord(unsigned u) {
    unsigned v = (u & 0x80000000u) ? (u & 0x7fffffffu) : ~u;
    return __uint_as_float(v);
}

__global__ void k_segmax(const float* __restrict__ gate, const int* __restrict__ batch,
                         unsigned* __restrict__ gmax, int Nn) {
    int i = blockIdx.x * blockDim.x + threadIdx.x;
    if (i >= Nn) return;
    atomicMax(&gmax[__ldg(&batch[i])], enc_ord(__ldg(&gate[i])));
}

__global__ void k_segexp(const float* __restrict__ gate, const int* __restrict__ batch,
                         const unsigned* __restrict__ gmax, float* __restrict__ ex,
                         float* __restrict__ den, int Nn) {
    int i = blockIdx.x * blockDim.x + threadIdx.x;
    if (i >= Nn) return;
    int b = __ldg(&batch[i]);
    float e = expf(__ldg(&gate[i]) - dec_ord(gmax[b]));
    ex[i] = e;
    atomicAdd(&den[b], e);
}

__global__ void k_pool(const float* __restrict__ h, const int* __restrict__ batch,
                       const float* __restrict__ ex, const float* __restrict__ den,
                       float* __restrict__ pooled, int Nn) {
    int gid = blockIdx.x * blockDim.x + threadIdx.x;
    int i = gid >> 6;      // node
    int q = gid & 63;      // float4 index in 256-wide row
    if (i >= Nn) return;
    int b = __ldg(&batch[i]);
    float alpha = __ldg(&ex[i]) / __ldg(&den[b]);
    float4 v = __ldg(&((const float4*)(h + (size_t)i * 256))[q]);
    v.x *= alpha; v.y *= alpha; v.z *= alpha; v.w *= alpha;
    red_add_v4(pooled + (size_t)b * 256 + q * 4, v);
}

// ---------------------------- classifier ------------------------------------
__global__ void __launch_bounds__(128)
k_cls(const float* __restrict__ pooled, const float* __restrict__ w1,
      const float* __restrict__ b1, const float* __restrict__ w2,
      const float* __restrict__ b2, float* __restrict__ out) {
    __shared__ float sp[256];
    __shared__ float r0s[4], r1s[4];
    int g = blockIdx.x;
    int tid = threadIdx.x;
    sp[tid] = pooled[(size_t)g * 256 + tid];
    sp[tid + 128] = pooled[(size_t)g * 256 + tid + 128];
    __syncthreads();
    float acc = __ldg(&b1[tid]);
#pragma unroll 8
    for (int k = 0; k < 256; k++) acc += sp[k] * __ldg(&w1[k * 128 + tid]);
    float q = fmaxf(acc, 0.f);
    float o0 = q * __ldg(&w2[tid * 2 + 0]);
    float o1 = q * __ldg(&w2[tid * 2 + 1]);
#pragma unroll
    for (int off = 16; off > 0; off >>= 1) {
        o0 += __shfl_xor_sync(0xffffffffu, o0, off);
        o1 += __shfl_xor_sync(0xffffffffu, o1, off);
    }
    int wid = tid >> 5, lane = tid & 31;
    if (lane == 0) { r0s[wid] = o0; r1s[wid] = o1; }
    __syncthreads();
    if (tid == 0) {
        float s0 = r0s[0] + r0s[1] + r0s[2] + r0s[3];
        float s1 = r1s[0] + r1s[1] + r1s[2] + r1s[3];
        out[g * 2 + 0] = s0 + __ldg(&b2[0]);
        out[g * 2 + 1] = s1 + __ldg(&b2[1]);
    }
}

// ---------------------------------------------------------------------------
extern "C" void kernel_launch(void* const* d_in, const int* in_sizes, int n_in,
                              void* d_out, int out_size) {
    const float* x       = (const float*)d_in[0];
    const int*   ei      = (const int*)d_in[1];
    const int*   batch   = (const int*)d_in[2];
    const float* w1_0    = (const float*)d_in[4];
    const float* b1_0    = (const float*)d_in[5];
    const float* w2_0    = (const float*)d_in[6];
    const float* b2_0    = (const float*)d_in[7];
    const float* ln_g0   = (const float*)d_in[8];
    const float* ln_b0   = (const float*)d_in[9];
    const float* w1_1    = (const float*)d_in[10];
    const float* b1_1    = (const float*)d_in[11];
    const float* w2_1    = (const float*)d_in[12];
    const float* b2_1    = (const float*)d_in[13];
    const float* ln_g1   = (const float*)d_in[14];
    const float* ln_b1   = (const float*)d_in[15];
    const float* gate_w1 = (const float*)d_in[16];
    const float* gate_b1 = (const float*)d_in[17];
    const float* gate_w2 = (const float*)d_in[18];
    const float* gate_b2 = (const float*)d_in[19];
    const float* cls_w1  = (const float*)d_in[20];
    const float* cls_b1  = (const float*)d_in[21];
    const float* cls_w2  = (const float*)d_in[22];
    const float* cls_b2  = (const float*)d_in[23];
    float* out = (float*)d_out;

    const int N = in_sizes[0] / 128;
    const int E = in_sizes[1] / 2;
    const int G = out_size / 2;
    const int* src = ei;
    const int* dst = ei + E;

    float *bufA, *bufB, *bufC, *gate, *ex, *den, *pooled;
    unsigned* gmax;
    cudaGetSymbolAddress((void**)&bufA, g_bufA);
    cudaGetSymbolAddress((void**)&bufB, g_bufB);
    cudaGetSymbolAddress((void**)&bufC, g_bufC);
    cudaGetSymbolAddress((void**)&gate, g_gate);
    cudaGetSymbolAddress((void**)&ex, g_exp);
    cudaGetSymbolAddress((void**)&gmax, g_gmax);
    cudaGetSymbolAddress((void**)&den, g_den);
    cudaGetSymbolAddress((void**)&pooled, g_pooled);

    const int ZT = 256;
    dim3 gemm_grid_256(2, cdiv(N, 128));
    dim3 gemm_grid_128(1, cdiv(N, 128));
    int scat_blocks = cdiv(E * 32, 256);

    // ---- layer 0 ----
    k_zero4<<<cdiv(N * 32, ZT), ZT>>>((float4*)bufA, N * 32);         // N*128 floats
    k_scatter<128><<<scat_blocks, 256>>>(x, src, dst, bufA, E);
    k_gemm<true, true><<<gemm_grid_256, 256>>>(x, bufA, w1_0, b1_0, bufB, N, 128, 256);
    k_gemm<false, false><<<gemm_grid_256, 256>>>(bufB, nullptr, w2_0, b2_0, bufC, N, 256, 256);
    k_ln<<<cdiv(N, 8), 256>>>(bufC, ln_g0, ln_b0, N);

    // ---- layer 1 ----
    k_zero4<<<cdiv(N * 64, ZT), ZT>>>((float4*)bufA, N * 64);         // N*256 floats
    k_scatter<256><<<scat_blocks, 256>>>(bufC, src, dst, bufA, E);
    k_gemm<true, true><<<gemm_grid_256, 256>>>(bufC, bufA, w1_1, b1_1, bufB, N, 256, 256);
    k_gemm<false, false><<<gemm_grid_256, 256>>>(bufB, nullptr, w2_1, b2_1, bufA, N, 256, 256);
    k_ln<<<cdiv(N, 8), 256>>>(bufA, ln_g1, ln_b1, N);                 // bufA = h1

    // ---- gate ----
    k_gemm<false, true><<<gemm_grid_128, 256>>>(bufA, nullptr, gate_w1, gate_b1, bufB, N, 256, 128);
    k_gatedot<<<cdiv(N, 8), 256>>>(bufB, gate_w2, gate_b2, gate, N);

    // ---- segment softmax + pooled ----
    k_zero_small<<<cdiv(G * 256, ZT), ZT>>>(gmax, den, pooled, G);
    k_segmax<<<cdiv(N, 256), 256>>>(gate, batch, gmax, N);
    k_segexp<<<cdiv(N, 256), 256>>>(gate, batch, gmax, ex, den, N);
    k_pool<<<cdiv(N * 64, 256), 256>>>(bufA, batch, ex, den, pooled, N);

    // ---- classifier ----
    k_cls<<<G, 128>>>(pooled, cls_w1, cls_b1, cls_w2, cls_b2, out);
}

// round 2
// speedup vs baseline: 1.1555x; 1.1555x over previous
#include <cuda_runtime.h>
#include <cstdint>
#include <cstddef>

// ---------------------------------------------------------------------------
// DynamicGIN on GB300 — round 2: GEMMs on tensor cores via 3xTF32 mma.sync
// ---------------------------------------------------------------------------

#define NMAX 100000
#define GMAXC 1024

__device__ float g_bufA[(size_t)NMAX * 256]; // agg scratch, later h1
__device__ float g_bufB[(size_t)NMAX * 256]; // MLP mid scratch
__device__ float g_bufC[(size_t)NMAX * 256]; // h0
__device__ float g_gate[NMAX];
__device__ float g_exp[NMAX];
__device__ unsigned g_gmax[GMAXC];
__device__ float g_den[GMAXC];
__device__ float g_pooled[GMAXC * 256];

static inline int cdiv(int a, int b) { return (a + b - 1) / b; }

// ---------------------------- zero kernels ---------------------------------
__global__ void k_zero4(float4* __restrict__ p, int n4) {
    int i = blockIdx.x * blockDim.x + threadIdx.x;
    if (i < n4) p[i] = make_float4(0.f, 0.f, 0.f, 0.f);
}

__global__ void k_zero_small(unsigned* __restrict__ gmax, float* __restrict__ den,
                             float* __restrict__ pooled, int G) {
    int i = blockIdx.x * blockDim.x + threadIdx.x;
    if (i < G) { gmax[i] = 0u; den[i] = 0.f; }
    if (i < G * 256) pooled[i] = 0.f;
}

// ---------------------------- edge scatter ---------------------------------
__device__ __forceinline__ void red_add_v4(float* addr, float4 v) {
    asm volatile("red.global.add.v4.f32 [%0], {%1,%2,%3,%4};"
                 :: "l"(addr), "f"(v.x), "f"(v.y), "f"(v.z), "f"(v.w)
                 : "memory");
}

template <int F>
__global__ void k_scatter(const float* __restrict__ x, const int* __restrict__ src,
                          const int* __restrict__ dst, float* __restrict__ agg, int E) {
    int gid = blockIdx.x * blockDim.x + threadIdx.x;
    int e = gid >> 5;
    int lane = gid & 31;
    if (e >= E) return;
    int s = __ldg(&src[e]);
    int d = __ldg(&dst[e]);
    const float4* xs = (const float4*)(x + (size_t)s * F);
    float* ag = agg + (size_t)d * F;
#pragma unroll
    for (int i = 0; i < F / 128; i++) {
        int q = lane + i * 32;           // float4 index within row
        float4 v = __ldg(&xs[q]);
        red_add_v4(ag + q * 4, v);
    }
}

// ---------------------------- 3xTF32 tensor-core GEMM ----------------------
// C[M,N] = epilogue( (A (+A2)) @ W + bias ), fp32 in/out, tf32 split hi/lo.
// Block 128x128, BK=16, 256 threads = 8 warps, warp tile 64x32 (2Mx4N warps).

__device__ __forceinline__ unsigned f2tf32(float x) {
    unsigned r;
    asm("cvt.rna.tf32.f32 %0, %1;" : "=r"(r) : "f"(x));
    return r;
}

#define MMA_TF32(d, a, b)                                                      \
    asm volatile(                                                              \
        "mma.sync.aligned.m16n8k8.row.col.f32.tf32.tf32.f32 "                  \
        "{%0,%1,%2,%3}, {%4,%5,%6,%7}, {%8,%9}, {%0,%1,%2,%3};"                \
        : "+f"(d[0]), "+f"(d[1]), "+f"(d[2]), "+f"(d[3])                       \
        : "r"(a[0]), "r"(a[1]), "r"(a[2]), "r"(a[3]), "r"(b[0]), "r"(b[1]))

template <bool ADD2, bool RELU>
__global__ void __launch_bounds__(256)
k_gemm_tc(const float* __restrict__ A, const float* __restrict__ A2,
          const float* __restrict__ W, const float* __restrict__ bias,
          float* __restrict__ C, int M, int K, int N) {
    __shared__ float As_hi[128][20];   // [m][k], stride 20 -> conflict-free frags
    __shared__ float As_lo[128][20];
    __shared__ float Bs_hi[16][136];   // [k][n], stride 136 -> conflict-free frags
    __shared__ float Bs_lo[16][136];

    const int tid = threadIdx.x;
    const int lane = tid & 31;
    const int wid = tid >> 5;
    const int g = lane >> 2;     // groupID 0..7
    const int t = lane & 3;      // thread-in-group 0..3
    const int warpM = wid >> 2;  // 0..1
    const int warpN = wid & 3;   // 0..3
    const int mb = warpM * 64;
    const int nb = warpN * 32;
    const int row0 = blockIdx.y * 128;
    const int col0 = blockIdx.x * 128;

    float acc[4][4][4];
#pragma unroll
    for (int i = 0; i < 4; i++)
#pragma unroll
        for (int j = 0; j < 4; j++)
#pragma unroll
            for (int r = 0; r < 4; r++) acc[i][j][r] = 0.f;

    for (int k0 = 0; k0 < K; k0 += 16) {
        // --- load A tile: 128 rows x 16 k, split into tf32 hi/lo ---
#pragma unroll
        for (int tl = 0; tl < 2; tl++) {
            int idx = tid + tl * 256;      // 0..511 float4 slots
            int r = idx >> 2;              // 0..127
            int c = (idx & 3) * 4;         // 0,4,8,12
            int gr = row0 + r;
            float4 v = make_float4(0.f, 0.f, 0.f, 0.f);
            if (gr < M) {
                v = *(const float4*)(A + (size_t)gr * K + k0 + c);
                if (ADD2) {
                    float4 w = *(const float4*)(A2 + (size_t)gr * K + k0 + c);
                    v.x += w.x; v.y += w.y; v.z += w.z; v.w += w.w;
                }
            }
            float4 h, l;
            h.x = __uint_as_float(f2tf32(v.x)); l.x = __uint_as_float(f2tf32(v.x - h.x));
            h.y = __uint_as_float(f2tf32(v.y)); l.y = __uint_as_float(f2tf32(v.y - h.y));
            h.z = __uint_as_float(f2tf32(v.z)); l.z = __uint_as_float(f2tf32(v.z - h.z));
            h.w = __uint_as_float(f2tf32(v.w)); l.w = __uint_as_float(f2tf32(v.w - h.w));
            *(float4*)&As_hi[r][c] = h;
            *(float4*)&As_lo[r][c] = l;
        }
        // --- load B tile: 16 k x 128 n ---
#pragma unroll
        for (int tl = 0; tl < 2; tl++) {
            int idx = tid + tl * 256;
            int r = idx >> 5;              // 0..15
            int c = (idx & 31) * 4;        // 0..124
            float4 v = *(const float4*)(W + (size_t)(k0 + r) * N + col0 + c);
            float4 h, l;
            h.x = __uint_as_float(f2tf32(v.x)); l.x = __uint_as_float(f2tf32(v.x - h.x));
            h.y = __uint_as_float(f2tf32(v.y)); l.y = __uint_as_float(f2tf32(v.y - h.y));
            h.z = __uint_as_float(f2tf32(v.z)); l.z = __uint_as_float(f2tf32(v.z - h.z));
            h.w = __uint_as_float(f2tf32(v.w)); l.w = __uint_as_float(f2tf32(v.w - h.w));
            *(float4*)&Bs_hi[r][c] = h;
            *(float4*)&Bs_lo[r][c] = l;
        }
        __syncthreads();

#pragma unroll
        for (int ks = 0; ks < 2; ks++) {
            const int kk = ks * 8;
            unsigned ah[4][4], al[4][4], bh[4][2], bl[4][2];
#pragma unroll
            for (int mf = 0; mf < 4; mf++) {
                int r = mb + mf * 16 + g;
                ah[mf][0] = __float_as_uint(As_hi[r][kk + t]);
                ah[mf][1] = __float_as_uint(As_hi[r + 8][kk + t]);
                ah[mf][2] = __float_as_uint(As_hi[r][kk + t + 4]);
                ah[mf][3] = __float_as_uint(As_hi[r + 8][kk + t + 4]);
                al[mf][0] = __float_as_uint(As_lo[r][kk + t]);
                al[mf][1] = __float_as_uint(As_lo[r + 8][kk + t]);
                al[mf][2] = __float_as_uint(As_lo[r][kk + t + 4]);
                al[mf][3] = __float_as_uint(As_lo[r + 8][kk + t + 4]);
            }
#pragma unroll
            for (int nf = 0; nf < 4; nf++) {
                int c = nb + nf * 8 + g;
                bh[nf][0] = __float_as_uint(Bs_hi[kk + t][c]);
                bh[nf][1] = __float_as_uint(Bs_hi[kk + t + 4][c]);
                bl[nf][0] = __float_as_uint(Bs_lo[kk + t][c]);
                bl[nf][1] = __float_as_uint(Bs_lo[kk + t + 4][c]);
            }
#pragma unroll
            for (int mf = 0; mf < 4; mf++)
#pragma unroll
                for (int nf = 0; nf < 4; nf++) {
                    MMA_TF32(acc[mf][nf], al[mf], bh[nf]);  // lo*hi
                    MMA_TF32(acc[mf][nf], ah[mf], bl[nf]);  // hi*lo
                    MMA_TF32(acc[mf][nf], ah[mf], bh[nf]);  // hi*hi
                }
        }
        __syncthreads();
    }

    // --- epilogue: bias (+ReLU), c0/c1 at (row, 2t), c2/c3 at (row+8, 2t) ---
#pragma unroll
    for (int mf = 0; mf < 4; mf++) {
        int r0 = row0 + mb + mf * 16 + g;
        int r1 = r0 + 8;
#pragma unroll
        for (int nf = 0; nf < 4; nf++) {
            int c = col0 + nb + nf * 8 + 2 * t;
            float bx = __ldg(&bias[c]);
            float by = __ldg(&bias[c + 1]);
            float v0 = acc[mf][nf][0] + bx;
            float v1 = acc[mf][nf][1] + by;
            float v2 = acc[mf][nf][2] + bx;
            float v3 = acc[mf][nf][3] + by;
            if (RELU) {
                v0 = fmaxf(v0, 0.f); v1 = fmaxf(v1, 0.f);
                v2 = fmaxf(v2, 0.f); v3 = fmaxf(v3, 0.f);
            }
            if (r0 < M) { float2 o = {v0, v1}; *(float2*)(C + (size_t)r0 * N + c) = o; }
            if (r1 < M) { float2 o = {v2, v3}; *(float2*)(C + (size_t)r1 * N + c) = o; }
        }
    }
}

// ---------------------------- LayerNorm + ReLU (in place, 256 cols) --------
__global__ void k_ln(float* __restrict__ h, const float* __restrict__ gamma,
                     const float* __restrict__ beta, int M) {
    int row = blockIdx.x * 8 + (threadIdx.x >> 5);
    int lane = threadIdx.x & 31;
    if (row >= M) return;
    float4* p = (float4*)(h + (size_t)row * 256);
    float4 v0 = p[lane];
    float4 v1 = p[lane + 32];
    float s = v0.x + v0.y + v0.z + v0.w + v1.x + v1.y + v1.z + v1.w;
    float ss = v0.x * v0.x + v0.y * v0.y + v0.z * v0.z + v0.w * v0.w
             + v1.x * v1.x + v1.y * v1.y + v1.z * v1.z + v1.w * v1.w;
#pragma unroll
    for (int off = 16; off > 0; off >>= 1) {
        s  += __shfl_xor_sync(0xffffffffu, s, off);
        ss += __shfl_xor_sync(0xffffffffu, ss, off);
    }
    float mean = s * (1.f / 256.f);
    float var  = ss * (1.f / 256.f) - mean * mean;
    float inv  = rsqrtf(var + 1e-5f);
    const float4* g4 = (const float4*)gamma;
    const float4* b4 = (const float4*)beta;
    float4 g0 = __ldg(&g4[lane]),      b0 = __ldg(&b4[lane]);
    float4 g1 = __ldg(&g4[lane + 32]), b1 = __ldg(&b4[lane + 32]);
    float4 o0, o1;
    o0.x = fmaxf((v0.x - mean) * inv * g0.x + b0.x, 0.f);
    o0.y = fmaxf((v0.y - mean) * inv * g0.y + b0.y, 0.f);
    o0.z = fmaxf((v0.z - mean) * inv * g0.z + b0.z, 0.f);
    o0.w = fmaxf((v0.w - mean) * inv * g0.w + b0.w, 0.f);
    o1.x = fmaxf((v1.x - mean) * inv * g1.x + b1.x, 0.f);
    o1.y = fmaxf((v1.y - mean) * inv * g1.y + b1.y, 0.f);
    o1.z = fmaxf((v1.z - mean) * inv * g1.z + b1.z, 0.f);
    o1.w = fmaxf((v1.w - mean) * inv * g1.w + b1.w, 0.f);
    p[lane] = o0;
    p[lane + 32] = o1;
}

// ---------------------------- gate second layer (128 -> 1) -----------------
__global__ void k_gatedot(const float* __restrict__ t, const float* __restrict__ w2,
                          const float* __restrict__ b2, float* __restrict__ gate, int M) {
    int row = blockIdx.x * 8 + (threadIdx.x >> 5);
    int lane = threadIdx.x & 31;
    if (row >= M) return;
    float4 v = __ldg(&((const float4*)(t + (size_t)row * 128))[lane]);
    float4 w = __ldg(&((const float4*)w2)[lane]);
    float s = v.x * w.x + v.y * w.y + v.z * w.z + v.w * w.w;
#pragma unroll
    for (int off = 16; off > 0; off >>= 1)
        s += __shfl_xor_sync(0xffffffffu, s, off);
    if (lane == 0) gate[row] = s + __ldg(&b2[0]);
}

// ---------------------------- segment softmax + pool ------------------------
__device__ __forceinline__ unsigned enc_ord(float f) {
    unsigned u = __float_as_uint(f);
    return (u & 0x80000000u) ? ~u : (u | 0x80000000u);
}
__device__ __forceinline__ float dec_ord(unsigned u) {
    unsigned v = (u & 0x80000000u) ? (u & 0x7fffffffu) : ~u;
    return __uint_as_float(v);
}

__global__ void k_segmax(const float* __restrict__ gate, const int* __restrict__ batch,
                         unsigned* __restrict__ gmax, int Nn) {
    int i = blockIdx.x * blockDim.x + threadIdx.x;
    if (i >= Nn) return;
    atomicMax(&gmax[__ldg(&batch[i])], enc_ord(__ldg(&gate[i])));
}

__global__ void k_segexp(const float* __restrict__ gate, const int* __restrict__ batch,
                         const unsigned* __restrict__ gmax, float* __restrict__ ex,
                         float* __restrict__ den, int Nn) {
    int i = blockIdx.x * blockDim.x + threadIdx.x;
    if (i >= Nn) return;
    int b = __ldg(&batch[i]);
    float e = expf(__ldg(&gate[i]) - dec_ord(gmax[b]));
    ex[i] = e;
    atomicAdd(&den[b], e);
}

__global__ void k_pool(const float* __restrict__ h, const int* __restrict__ batch,
                       const float* __restrict__ ex, const float* __restrict__ den,
                       float* __restrict__ pooled, int Nn) {
    int gid = blockIdx.x * blockDim.x + threadIdx.x;
    int i = gid >> 6;      // node
    int q = gid & 63;      // float4 index in 256-wide row
    if (i >= Nn) return;
    int b = __ldg(&batch[i]);
    float alpha = __ldg(&ex[i]) / __ldg(&den[b]);
    float4 v = __ldg(&((const float4*)(h + (size_t)i * 256))[q]);
    v.x *= alpha; v.y *= alpha; v.z *= alpha; v.w *= alpha;
    red_add_v4(pooled + (size_t)b * 256 + q * 4, v);
}

// ---------------------------- classifier ------------------------------------
__global__ void __launch_bounds__(128)
k_cls(const float* __restrict__ pooled, const float* __restrict__ w1,
      const float* __restrict__ b1, const float* __restrict__ w2,
      const float* __restrict__ b2, float* __restrict__ out) {
    __shared__ float sp[256];
    __shared__ float r0s[4], r1s[4];
    int g = blockIdx.x;
    int tid = threadIdx.x;
    sp[tid] = pooled[(size_t)g * 256 + tid];
    sp[tid + 128] = pooled[(size_t)g * 256 + tid + 128];
    __syncthreads();
    float acc = __ldg(&b1[tid]);
#pragma unroll 8
    for (int k = 0; k < 256; k++) acc += sp[k] * __ldg(&w1[k * 128 + tid]);
    float q = fmaxf(acc, 0.f);
    float o0 = q * __ldg(&w2[tid * 2 + 0]);
    float o1 = q * __ldg(&w2[tid * 2 + 1]);
#pragma unroll
    for (int off = 16; off > 0; off >>= 1) {
        o0 += __shfl_xor_sync(0xffffffffu, o0, off);
        o1 += __shfl_xor_sync(0xffffffffu, o1, off);
    }
    int wid = tid >> 5, lane = tid & 31;
    if (lane == 0) { r0s[wid] = o0; r1s[wid] = o1; }
    __syncthreads();
    if (tid == 0) {
        float s0 = r0s[0] + r0s[1] + r0s[2] + r0s[3];
        float s1 = r1s[0] + r1s[1] + r1s[2] + r1s[3];
        out[g * 2 + 0] = s0 + __ldg(&b2[0]);
        out[g * 2 + 1] = s1 + __ldg(&b2[1]);
    }
}

// ---------------------------------------------------------------------------
extern "C" void kernel_launch(void* const* d_in, const int* in_sizes, int n_in,
                              void* d_out, int out_size) {
    const float* x       = (const float*)d_in[0];
    const int*   ei      = (const int*)d_in[1];
    const int*   batch   = (const int*)d_in[2];
    const float* w1_0    = (const float*)d_in[4];
    const float* b1_0    = (const float*)d_in[5];
    const float* w2_0    = (const float*)d_in[6];
    const float* b2_0    = (const float*)d_in[7];
    const float* ln_g0   = (const float*)d_in[8];
    const float* ln_b0   = (const float*)d_in[9];
    const float* w1_1    = (const float*)d_in[10];
    const float* b1_1    = (const float*)d_in[11];
    const float* w2_1    = (const float*)d_in[12];
    const float* b2_1    = (const float*)d_in[13];
    const float* ln_g1   = (const float*)d_in[14];
    const float* ln_b1   = (const float*)d_in[15];
    const float* gate_w1 = (const float*)d_in[16];
    const float* gate_b1 = (const float*)d_in[17];
    const float* gate_w2 = (const float*)d_in[18];
    const float* gate_b2 = (const float*)d_in[19];
    const float* cls_w1  = (const float*)d_in[20];
    const float* cls_b1  = (const float*)d_in[21];
    const float* cls_w2  = (const float*)d_in[22];
    const float* cls_b2  = (const float*)d_in[23];
    float* out = (float*)d_out;

    const int N = in_sizes[0] / 128;
    const int E = in_sizes[1] / 2;
    const int G = out_size / 2;
    const int* src = ei;
    const int* dst = ei + E;

    float *bufA, *bufB, *bufC, *gate, *ex, *den, *pooled;
    unsigned* gmax;
    cudaGetSymbolAddress((void**)&bufA, g_bufA);
    cudaGetSymbolAddress((void**)&bufB, g_bufB);
    cudaGetSymbolAddress((void**)&bufC, g_bufC);
    cudaGetSymbolAddress((void**)&gate, g_gate);
    cudaGetSymbolAddress((void**)&ex, g_exp);
    cudaGetSymbolAddress((void**)&gmax, g_gmax);
    cudaGetSymbolAddress((void**)&den, g_den);
    cudaGetSymbolAddress((void**)&pooled, g_pooled);

    const int ZT = 256;
    dim3 gemm_grid_256(2, cdiv(N, 128));
    dim3 gemm_grid_128(1, cdiv(N, 128));
    int scat_blocks = cdiv(E * 32, 256);

    // ---- layer 0 ----
    k_zero4<<<cdiv(N * 32, ZT), ZT>>>((float4*)bufA, N * 32);         // N*128 floats
    k_scatter<128><<<scat_blocks, 256>>>(x, src, dst, bufA, E);
    k_gemm_tc<true, true><<<gemm_grid_256, 256>>>(x, bufA, w1_0, b1_0, bufB, N, 128, 256);
    k_gemm_tc<false, false><<<gemm_grid_256, 256>>>(bufB, nullptr, w2_0, b2_0, bufC, N, 256, 256);
    k_ln<<<cdiv(N, 8), 256>>>(bufC, ln_g0, ln_b0, N);

    // ---- layer 1 ----
    k_zero4<<<cdiv(N * 64, ZT), ZT>>>((float4*)bufA, N * 64);         // N*256 floats
    k_scatter<256><<<scat_blocks, 256>>>(bufC, src, dst, bufA, E);
    k_gemm_tc<true, true><<<gemm_grid_256, 256>>>(bufC, bufA, w1_1, b1_1, bufB, N, 256, 256);
    k_gemm_tc<false, false><<<gemm_grid_256, 256>>>(bufB, nullptr, w2_1, b2_1, bufA, N, 256, 256);
    k_ln<<<cdiv(N, 8), 256>>>(bufA, ln_g1, ln_b1, N);                 // bufA = h1

    // ---- gate ----
    k_gemm_tc<false, true><<<gemm_grid_128, 256>>>(bufA, nullptr, gate_w1, gate_b1, bufB, N, 256, 128);
    k_gatedot<<<cdiv(N, 8), 256>>>(bufB, gate_w2, gate_b2, gate, N);

    // ---- segment softmax + pooled ----
    k_zero_small<<<cdiv(G * 256, ZT), ZT>>>(gmax, den, pooled, G);
    k_segmax<<<cdiv(N, 256), 256>>>(gate, batch, gmax, N);
    k_segexp<<<cdiv(N, 256), 256>>>(gate, batch, gmax, ex, den, N);
    k_pool<<<cdiv(N * 64, 256), 256>>>(bufA, batch, ex, den, pooled, N);

    // ---- classifier ----
    k_cls<<<G, 128>>>(pooled, cls_w1, cls_b1, cls_w2, cls_b2, out);
}

// round 8
// speedup vs baseline: 1.2852x; 1.1122x over previous
#include <cuda_runtime.h>
#include <cuda_bf16.h>
#include <cstdint>
#include <cstddef>

// ---------------------------------------------------------------------------
// DynamicGIN on GB300 — round 8 (= round 7 resubmit; infra timeout):
// GEMMs via mma.sync.m16n8k16 BF16x3
// (tcgen05 unavailable: harness ptxas targets sm_103 without 'a' suffix)
// ---------------------------------------------------------------------------

#define NMAX 100000
#define GMAXC 1024

__device__ float g_bufA[(size_t)NMAX * 256]; // agg scratch, later h1
__device__ float g_bufB[(size_t)NMAX * 256]; // MLP mid scratch
__device__ float g_bufC[(size_t)NMAX * 256]; // h0
__device__ float g_gate[NMAX];
__device__ float g_exp[NMAX];
__device__ unsigned g_gmax[GMAXC];
__device__ float g_den[GMAXC];
__device__ float g_pooled[GMAXC * 256];
// pre-split transposed packed-bf16 weights: [slot][hi/lo][N*K/2 u32]
__device__ uint32_t g_wt[5][2][256 * 128];

static inline int cdiv(int a, int b) { return (a + b - 1) / b; }

// ---------------------------- bf16 split helpers ----------------------------
__device__ __forceinline__ uint32_t packbf(float lo, float hi) {
    uint32_t r;
    asm("cvt.rn.bf16x2.f32 %0, %1, %2;" : "=r"(r) : "f"(hi), "f"(lo));
    return r;
}
__device__ __forceinline__ float lo_f(uint32_t p) { return __uint_as_float(p << 16); }
__device__ __forceinline__ float hi_f(uint32_t p) { return __uint_as_float(p & 0xFFFF0000u); }

// split float4 (4 consecutive k) into hi-pack pair and lo-pack pair
__device__ __forceinline__ void split4(float4 v, uint32_t& hp0, uint32_t& hp1,
                                       uint32_t& lp0, uint32_t& lp1) {
    hp0 = packbf(v.x, v.y);
    hp1 = packbf(v.z, v.w);
    lp0 = packbf(v.x - lo_f(hp0), v.y - hi_f(hp0));
    lp1 = packbf(v.z - lo_f(hp1), v.w - hi_f(hp1));
}

#define MMA_BF16(d, a, b)                                                      \
    asm volatile(                                                              \
        "mma.sync.aligned.m16n8k16.row.col.f32.bf16.bf16.f32 "                 \
        "{%0,%1,%2,%3}, {%4,%5,%6,%7}, {%8,%9}, {%0,%1,%2,%3};"                \
        : "+f"((d)[0]), "+f"((d)[1]), "+f"((d)[2]), "+f"((d)[3])               \
        : "r"((a)[0]), "r"((a)[1]), "r"((a)[2]), "r"((a)[3]),                  \
          "r"((b)[0]), "r"((b)[1]))

// ---------------------------- zero kernels ---------------------------------
__global__ void k_zero4(float4* __restrict__ p, int n4) {
    int i = blockIdx.x * blockDim.x + threadIdx.x;
    if (i < n4) p[i] = make_float4(0.f, 0.f, 0.f, 0.f);
}

__global__ void k_zero_small(unsigned* __restrict__ gmax, float* __restrict__ den,
                             float* __restrict__ pooled, int G) {
    int i = blockIdx.x * blockDim.x + threadIdx.x;
    if (i < G) { gmax[i] = 0u; den[i] = 0.f; }
    if (i < G * 256) pooled[i] = 0.f;
}

// -------- weight transpose + bf16 hi/lo split + k-pair pack (per launch) ----
__global__ void k_wsplit(const float* __restrict__ W, uint32_t* __restrict__ Whp,
                         uint32_t* __restrict__ Wlp, int K, int N) {
    int i = blockIdx.x * blockDim.x + threadIdx.x;
    int K2 = K >> 1;
    if (i >= N * K2) return;
    int n = i / K2, k2 = i % K2;
    float v0 = W[(size_t)(2 * k2) * N + n];
    float v1 = W[(size_t)(2 * k2 + 1) * N + n];
    uint32_t hp = packbf(v0, v1);
    uint32_t lp = packbf(v0 - lo_f(hp), v1 - hi_f(hp));
    Whp[(size_t)n * K2 + k2] = hp;
    Wlp[(size_t)n * K2 + k2] = lp;
}

// ---------------------------- edge scatter ---------------------------------
__device__ __forceinline__ void red_add_v4(float* addr, float4 v) {
    asm volatile("red.global.add.v4.f32 [%0], {%1,%2,%3,%4};"
                 :: "l"(addr), "f"(v.x), "f"(v.y), "f"(v.z), "f"(v.w)
                 : "memory");
}

template <int F>
__global__ void k_scatter(const float* __restrict__ x, const int* __restrict__ src,
                          const int* __restrict__ dst, float* __restrict__ agg, int E) {
    int gid = blockIdx.x * blockDim.x + threadIdx.x;
    int e = gid >> 5;
    int lane = gid & 31;
    if (e >= E) return;
    int s = __ldg(&src[e]);
    int d = __ldg(&dst[e]);
    const float4* xs = (const float4*)(x + (size_t)s * F);
    float* ag = agg + (size_t)d * F;
#pragma unroll
    for (int i = 0; i < F / 128; i++) {
        int q = lane + i * 32;
        float4 v = __ldg(&xs[q]);
        red_add_v4(ag + q * 4, v);
    }
}

// ---------------------------- BF16x3 tensor-core GEMM ----------------------
// C[M,N] = epilogue( (A (+A2)) @ W + bias ); W pre-transposed + split + packed:
// Whp/Wlp are [N][K/2] u32 (bf16x2 along k). Block 128x128, BK=32, 256 thr,
// 8 warps in 2Mx4N arrangement; warp tile 64x32; smem row stride 80B (=20 u32)
// -> fragment loads hit all 32 banks ((20g+t) mod 32 is a permutation).
template <bool ADD2, bool RELU>
__global__ void __launch_bounds__(256)
k_gemm_bf(const float* __restrict__ A, const float* __restrict__ A2,
          const uint32_t* __restrict__ Whp, const uint32_t* __restrict__ Wlp,
          const float* __restrict__ bias, float* __restrict__ C,
          int M, int K, int N) {
    __shared__ uint32_t As_hi[128 * 20];
    __shared__ uint32_t As_lo[128 * 20];
    __shared__ uint32_t Bs_hi[128 * 20];
    __shared__ uint32_t Bs_lo[128 * 20];

    const int tid = threadIdx.x;
    const int lane = tid & 31;
    const int wid = tid >> 5;
    const int g = lane >> 2;     // 0..7
    const int t = lane & 3;      // 0..3
    const int mb = (wid >> 2) * 64;
    const int nb = (wid & 3) * 32;
    const int row0 = blockIdx.y * 128;
    const int col0 = blockIdx.x * 128;
    const int K2 = K >> 1;

    float acc[4][4][4];
#pragma unroll
    for (int i = 0; i < 4; i++)
#pragma unroll
        for (int j = 0; j < 4; j++)
#pragma unroll
            for (int r = 0; r < 4; r++) acc[i][j][r] = 0.f;

    for (int k0 = 0; k0 < K; k0 += 32) {
        // --- A tile: 128 rows x 32 k floats -> bf16 hi/lo packs ---
#pragma unroll
        for (int i = 0; i < 4; i++) {
            int s = tid + i * 256;       // 0..1023 float4 slots
            int r = s >> 3, c4 = s & 7;  // row, float4-within-row (k = c4*4)
            int gr = row0 + r;
            float4 v = make_float4(0.f, 0.f, 0.f, 0.f);
            if (gr < M) {
                v = *(const float4*)(A + (size_t)gr * K + k0 + c4 * 4);
                if (ADD2) {
                    float4 w = *(const float4*)(A2 + (size_t)gr * K + k0 + c4 * 4);
                    v.x += w.x; v.y += w.y; v.z += w.z; v.w += w.w;
                }
            }
            uint32_t hp0, hp1, lp0, lp1;
            split4(v, hp0, hp1, lp0, lp1);
            int o = r * 20 + c4 * 2;
            As_hi[o] = hp0; As_hi[o + 1] = hp1;
            As_lo[o] = lp0; As_lo[o + 1] = lp1;
        }
        // --- B tile: 128 n-rows x 16 k-pairs (pre-packed) ---
#pragma unroll
        for (int i = 0; i < 8; i++) {
            int s = tid + i * 256;        // 0..2047 u32 slots
            int r = s >> 4, c2 = s & 15;  // n-row, k-pair
            size_t go = (size_t)(col0 + r) * K2 + (k0 >> 1) + c2;
            int o = r * 20 + c2;
            Bs_hi[o] = __ldg(&Whp[go]);
            Bs_lo[o] = __ldg(&Wlp[go]);
        }
        __syncthreads();

#pragma unroll
        for (int kk2 = 0; kk2 < 16; kk2 += 8) {   // two k16 slices (u32 units)
            uint32_t ah[4][4], al[4][4], bh[4][2], bl[4][2];
#pragma unroll
            for (int mf = 0; mf < 4; mf++) {
                int base = (mb + mf * 16 + g) * 20 + kk2 + t;
                ah[mf][0] = As_hi[base];
                ah[mf][1] = As_hi[base + 160];      // row + 8
                ah[mf][2] = As_hi[base + 4];        // k + 8
                ah[mf][3] = As_hi[base + 164];
                al[mf][0] = As_lo[base];
                al[mf][1] = As_lo[base + 160];
                al[mf][2] = As_lo[base + 4];
                al[mf][3] = As_lo[base + 164];
            }
#pragma unroll
            for (int nf = 0; nf < 4; nf++) {
                int base = (nb + nf * 8 + g) * 20 + kk2 + t;
                bh[nf][0] = Bs_hi[base];
                bh[nf][1] = Bs_hi[base + 4];
                bl[nf][0] = Bs_lo[base];
                bl[nf][1] = Bs_lo[base + 4];
            }
#pragma unroll
            for (int mf = 0; mf < 4; mf++)
#pragma unroll
                for (int nf = 0; nf < 4; nf++) {
                    MMA_BF16(acc[mf][nf], al[mf], bh[nf]);  // lo*hi
                    MMA_BF16(acc[mf][nf], ah[mf], bl[nf]);  // hi*lo
                    MMA_BF16(acc[mf][nf], ah[mf], bh[nf]);  // hi*hi
                }
        }
        __syncthreads();
    }

    // --- epilogue: c0/c1 at (row g, 2t), c2/c3 at (row g+8, 2t) ---
#pragma unroll
    for (int mf = 0; mf < 4; mf++) {
        int r0 = row0 + mb + mf * 16 + g;
        int r1 = r0 + 8;
#pragma unroll
        for (int nf = 0; nf < 4; nf++) {
            int c = col0 + nb + nf * 8 + 2 * t;
            float bx = __ldg(&bias[c]);
            float by = __ldg(&bias[c + 1]);
            float v0 = acc[mf][nf][0] + bx;
            float v1 = acc[mf][nf][1] + by;
            float v2 = acc[mf][nf][2] + bx;
            float v3 = acc[mf][nf][3] + by;
            if (RELU) {
                v0 = fmaxf(v0, 0.f); v1 = fmaxf(v1, 0.f);
                v2 = fmaxf(v2, 0.f); v3 = fmaxf(v3, 0.f);
            }
            if (r0 < M) { float2 o = {v0, v1}; *(float2*)(C + (size_t)r0 * N + c) = o; }
            if (r1 < M) { float2 o = {v2, v3}; *(float2*)(C + (size_t)r1 * N + c) = o; }
        }
    }
}

// ---------------------------- LayerNorm + ReLU (in place, 256 cols) --------
__global__ void k_ln(float* __restrict__ h, const float* __restrict__ gamma,
                     const float* __restrict__ beta, int M) {
    int row = blockIdx.x * 8 + (threadIdx.x >> 5);
    int lane = threadIdx.x & 31;
    if (row >= M) return;
    float4* p = (float4*)(h + (size_t)row * 256);
    float4 v0 = p[lane];
    float4 v1 = p[lane + 32];
    float s = v0.x + v0.y + v0.z + v0.w + v1.x + v1.y + v1.z + v1.w;
    float ss = v0.x * v0.x + v0.y * v0.y + v0.z * v0.z + v0.w * v0.w
             + v1.x * v1.x + v1.y * v1.y + v1.z * v1.z + v1.w * v1.w;
#pragma unroll
    for (int off = 16; off > 0; off >>= 1) {
        s  += __shfl_xor_sync(0xffffffffu, s, off);
        ss += __shfl_xor_sync(0xffffffffu, ss, off);
    }
    float mean = s * (1.f / 256.f);
    float var  = ss * (1.f / 256.f) - mean * mean;
    float inv  = rsqrtf(var + 1e-5f);
    const float4* g4 = (const float4*)gamma;
    const float4* b4 = (const float4*)beta;
    float4 g0 = __ldg(&g4[lane]),      b0 = __ldg(&b4[lane]);
    float4 g1 = __ldg(&g4[lane + 32]), b1 = __ldg(&b4[lane + 32]);
    float4 o0, o1;
    o0.x = fmaxf((v0.x - mean) * inv * g0.x + b0.x, 0.f);
    o0.y = fmaxf((v0.y - mean) * inv * g0.y + b0.y, 0.f);
    o0.z = fmaxf((v0.z - mean) * inv * g0.z + b0.z, 0.f);
    o0.w = fmaxf((v0.w - mean) * inv * g0.w + b0.w, 0.f);
    o1.x = fmaxf((v1.x - mean) * inv * g1.x + b1.x, 0.f);
    o1.y = fmaxf((v1.y - mean) * inv * g1.y + b1.y, 0.f);
    o1.z = fmaxf((v1.z - mean) * inv * g1.z + b1.z, 0.f);
    o1.w = fmaxf((v1.w - mean) * inv * g1.w + b1.w, 0.f);
    p[lane] = o0;
    p[lane + 32] = o1;
}

// ---------------------------- gate second layer (128 -> 1) -----------------
__global__ void k_gatedot(const float* __restrict__ t, const float* __restrict__ w2,
                          const float* __restrict__ b2, float* __restrict__ gate, int M) {
    int row = blockIdx.x * 8 + (threadIdx.x >> 5);
    int lane = threadIdx.x & 31;
    if (row >= M) return;
    float4 v = __ldg(&((const float4*)(t + (size_t)row * 128))[lane]);
    float4 w = __ldg(&((const float4*)w2)[lane]);
    float s = v.x * w.x + v.y * w.y + v.z * w.z + v.w * w.w;
#pragma unroll
    for (int off = 16; off > 0; off >>= 1)
        s += __shfl_xor_sync(0xffffffffu, s, off);
    if (lane == 0) gate[row] = s + __ldg(&b2[0]);
}

// ---------------------------- segment softmax + pool ------------------------
__device__ __forceinline__ unsigned enc_ord(float f) {
    unsigned u = __float_as_uint(f);
    return (u & 0x80000000u) ? ~u : (u | 0x80000000u);
}
__device__ __forceinline__ float dec_ord(unsigned u) {
    unsigned v = (u & 0x80000000u) ? (u & 0x7fffffffu) : ~u;
    return __uint_as_float(v);
}

__global__ void k_segmax(const float* __restrict__ gate, const int* __restrict__ batch,
                         unsigned* __restrict__ gmax, int Nn) {
    int i = blockIdx.x * blockDim.x + threadIdx.x;
    if (i >= Nn) return;
    atomicMax(&gmax[__ldg(&batch[i])], enc_ord(__ldg(&gate[i])));
}

__global__ void k_segexp(const float* __restrict__ gate, const int* __restrict__ batch,
                         const unsigned* __restrict__ gmax, float* __restrict__ ex,
                         float* __restrict__ den, int Nn) {
    int i = blockIdx.x * blockDim.x + threadIdx.x;
    if (i >= Nn) return;
    int b = __ldg(&batch[i]);
    float e = expf(__ldg(&gate[i]) - dec_ord(gmax[b]));
    ex[i] = e;
    atomicAdd(&den[b], e);
}

__global__ void k_pool(const float* __restrict__ h, const int* __restrict__ batch,
                       const float* __restrict__ ex, const float* __restrict__ den,
                       float* __restrict__ pooled, int Nn) {
    int gid = blockIdx.x * blockDim.x + threadIdx.x;
    int i = gid >> 6;
    int q = gid & 63;
    if (i >= Nn) return;
    int b = __ldg(&batch[i]);
    float alpha = __ldg(&ex[i]) / __ldg(&den[b]);
    float4 v = __ldg(&((const float4*)(h + (size_t)i * 256))[q]);
    v.x *= alpha; v.y *= alpha; v.z *= alpha; v.w *= alpha;
    red_add_v4(pooled + (size_t)b * 256 + q * 4, v);
}

// ---------------------------- classifier ------------------------------------
__global__ void __launch_bounds__(128)
k_cls(const float* __restrict__ pooled, const float* __restrict__ w1,
      const float* __restrict__ b1, const float* __restrict__ w2,
      const float* __restrict__ b2, float* __restrict__ out) {
    __shared__ float sp[256];
    __shared__ float r0s[4], r1s[4];
    int g = blockIdx.x;
    int tid = threadIdx.x;
    sp[tid] = pooled[(size_t)g * 256 + tid];
    sp[tid + 128] = pooled[(size_t)g * 256 + tid + 128];
    __syncthreads();
    float acc = __ldg(&b1[tid]);
#pragma unroll 8
    for (int k = 0; k < 256; k++) acc += sp[k] * __ldg(&w1[k * 128 + tid]);
    float q = fmaxf(acc, 0.f);
    float o0 = q * __ldg(&w2[tid * 2 + 0]);
    float o1 = q * __ldg(&w2[tid * 2 + 1]);
#pragma unroll
    for (int off = 16; off > 0; off >>= 1) {
        o0 += __shfl_xor_sync(0xffffffffu, o0, off);
        o1 += __shfl_xor_sync(0xffffffffu, o1, off);
    }
    int wid = tid >> 5, lane = tid & 31;
    if (lane == 0) { r0s[wid] = o0; r1s[wid] = o1; }
    __syncthreads();
    if (tid == 0) {
        float s0 = r0s[0] + r0s[1] + r0s[2] + r0s[3];
        float s1 = r1s[0] + r1s[1] + r1s[2] + r1s[3];
        out[g * 2 + 0] = s0 + __ldg(&b2[0]);
        out[g * 2 + 1] = s1 + __ldg(&b2[1]);
    }
}

// ---------------------------------------------------------------------------
extern "C" void kernel_launch(void* const* d_in, const int* in_sizes, int n_in,
                              void* d_out, int out_size) {
    const float* x       = (const float*)d_in[0];
    const int*   ei      = (const int*)d_in[1];
    const int*   batch   = (const int*)d_in[2];
    const float* w1_0    = (const float*)d_in[4];
    const float* b1_0    = (const float*)d_in[5];
    const float* w2_0    = (const float*)d_in[6];
    const float* b2_0    = (const float*)d_in[7];
    const float* ln_g0   = (const float*)d_in[8];
    const float* ln_b0   = (const float*)d_in[9];
    const float* w1_1    = (const float*)d_in[10];
    const float* b1_1    = (const float*)d_in[11];
    const float* w2_1    = (const float*)d_in[12];
    const float* b2_1    = (const float*)d_in[13];
    const float* ln_g1   = (const float*)d_in[14];
    const float* ln_b1   = (const float*)d_in[15];
    const float* gate_w1 = (const float*)d_in[16];
    const float* gate_b1 = (const float*)d_in[17];
    const float* gate_w2 = (const float*)d_in[18];
    const float* gate_b2 = (const float*)d_in[19];
    const float* cls_w1  = (const float*)d_in[20];
    const float* cls_b1  = (const float*)d_in[21];
    const float* cls_w2  = (const float*)d_in[22];
    const float* cls_b2  = (const float*)d_in[23];
    float* out = (float*)d_out;

    const int N = in_sizes[0] / 128;
    const int E = in_sizes[1] / 2;
    const int G = out_size / 2;
    const int* src = ei;
    const int* dst = ei + E;

    float *bufA, *bufB, *bufC, *gate, *ex, *den, *pooled;
    unsigned* gmax;
    uint32_t* wt;
    cudaGetSymbolAddress((void**)&bufA, g_bufA);
    cudaGetSymbolAddress((void**)&bufB, g_bufB);
    cudaGetSymbolAddress((void**)&bufC, g_bufC);
    cudaGetSymbolAddress((void**)&gate, g_gate);
    cudaGetSymbolAddress((void**)&ex, g_exp);
    cudaGetSymbolAddress((void**)&gmax, g_gmax);
    cudaGetSymbolAddress((void**)&den, g_den);
    cudaGetSymbolAddress((void**)&pooled, g_pooled);
    cudaGetSymbolAddress((void**)&wt, g_wt);

    // wt slots: [slot][hi=0/lo=1][256*128 u32]
    const size_t WS = 256 * 128;
    uint32_t* w10h = wt + 0 * 2 * WS; uint32_t* w10l = w10h + WS;
    uint32_t* w20h = wt + 1 * 2 * WS; uint32_t* w20l = w20h + WS;
    uint32_t* w11h = wt + 2 * 2 * WS; uint32_t* w11l = w11h + WS;
    uint32_t* w21h = wt + 3 * 2 * WS; uint32_t* w21l = w21h + WS;
    uint32_t* gw1h = wt + 4 * 2 * WS; uint32_t* gw1l = gw1h + WS;

    const int ZT = 256;
    dim3 g256(2, cdiv(N, 128));
    dim3 g128(1, cdiv(N, 128));
    int scat_blocks = cdiv(E * 32, 256);

    // ---- weight preprocessing (every launch, deterministic, ~tiny) ----
    k_wsplit<<<cdiv(256 * 64, 256), 256>>>(w1_0, w10h, w10l, 128, 256);
    k_wsplit<<<cdiv(256 * 128, 256), 256>>>(w2_0, w20h, w20l, 256, 256);
    k_wsplit<<<cdiv(256 * 128, 256), 256>>>(w1_1, w11h, w11l, 256, 256);
    k_wsplit<<<cdiv(256 * 128, 256), 256>>>(w2_1, w21h, w21l, 256, 256);
    k_wsplit<<<cdiv(128 * 128, 256), 256>>>(gate_w1, gw1h, gw1l, 256, 128);

    // ---- layer 0 ----
    k_zero4<<<cdiv(N * 32, ZT), ZT>>>((float4*)bufA, N * 32);
    k_scatter<128><<<scat_blocks, 256>>>(x, src, dst, bufA, E);
    k_gemm_bf<true, true><<<g256, 256>>>(x, bufA, w10h, w10l, b1_0, bufB, N, 128, 256);
    k_gemm_bf<false, false><<<g256, 256>>>(bufB, nullptr, w20h, w20l, b2_0, bufC, N, 256, 256);
    k_ln<<<cdiv(N, 8), 256>>>(bufC, ln_g0, ln_b0, N);

    // ---- layer 1 ----
    k_zero4<<<cdiv(N * 64, ZT), ZT>>>((float4*)bufA, N * 64);
    k_scatter<256><<<scat_blocks, 256>>>(bufC, src, dst, bufA, E);
    k_gemm_bf<true, true><<<g256, 256>>>(bufC, bufA, w11h, w11l, b1_1, bufB, N, 256, 256);
    k_gemm_bf<false, false><<<g256, 256>>>(bufB, nullptr, w21h, w21l, b2_1, bufA, N, 256, 256);
    k_ln<<<cdiv(N, 8), 256>>>(bufA, ln_g1, ln_b1, N);                 // bufA = h1

    // ---- gate ----
    k_gemm_bf<false, true><<<g128, 256>>>(bufA, nullptr, gw1h, gw1l, gate_b1, bufB, N, 256, 128);
    k_gatedot<<<cdiv(N, 8), 256>>>(bufB, gate_w2, gate_b2, gate, N);

    // ---- segment softmax + pooled ----
    k_zero_small<<<cdiv(G * 256, ZT), ZT>>>(gmax, den, pooled, G);
    k_segmax<<<cdiv(N, 256), 256>>>(gate, batch, gmax, N);
    k_segexp<<<cdiv(N, 256), 256>>>(gate, batch, gmax, ex, den, N);
    k_pool<<<cdiv(N * 64, 256), 256>>>(bufA, batch, ex, den, pooled, N);

    // ---- classifier ----
    k_cls<<<G, 128>>>(pooled, cls_w1, cls_b1, cls_w2, cls_b2, out);
}

// round 13
// speedup vs baseline: 1.7094x; 1.3301x over previous
#include <cuda_runtime.h>
#include <cuda_bf16.h>
#include <cstdint>
#include <cstddef>

// ---------------------------------------------------------------------------
// DynamicGIN on GB300 — round 13 (= round 9 resubmit; repeated infra timeouts):
// CSR-gather aggregation (no atomics, no zero) + BF16x3 mma.sync GEMMs
// ---------------------------------------------------------------------------

#define NMAX 100000
#define EMAX 1700000
#define GMAXC 1024

__device__ float g_bufA[(size_t)NMAX * 256]; // agg+self, later h1
__device__ float g_bufB[(size_t)NMAX * 256]; // MLP mid scratch
__device__ float g_bufC[(size_t)NMAX * 256]; // h0
__device__ float g_gate[NMAX];
__device__ float g_exp[NMAX];
__device__ unsigned g_gmax[GMAXC];
__device__ float g_den[GMAXC];
__device__ float g_pooled[GMAXC * 256];
__device__ uint32_t g_wt[5][2][256 * 128];   // packed bf16 weights [slot][hi/lo]
// CSR scratch
__device__ int g_deg[NMAX];
__device__ int g_off[NMAX + 1];
__device__ int g_cur[NMAX];
__device__ int g_csr[EMAX];
__device__ int g_bsum[512];

static inline int cdiv(int a, int b) { return (a + b - 1) / b; }

// ---------------------------- bf16 split helpers ----------------------------
__device__ __forceinline__ uint32_t packbf(float lo, float hi) {
    uint32_t r;
    asm("cvt.rn.bf16x2.f32 %0, %1, %2;" : "=r"(r) : "f"(hi), "f"(lo));
    return r;
}
__device__ __forceinline__ float lo_f(uint32_t p) { return __uint_as_float(p << 16); }
__device__ __forceinline__ float hi_f(uint32_t p) { return __uint_as_float(p & 0xFFFF0000u); }

__device__ __forceinline__ void split4(float4 v, uint32_t& hp0, uint32_t& hp1,
                                       uint32_t& lp0, uint32_t& lp1) {
    hp0 = packbf(v.x, v.y);
    hp1 = packbf(v.z, v.w);
    lp0 = packbf(v.x - lo_f(hp0), v.y - hi_f(hp0));
    lp1 = packbf(v.z - lo_f(hp1), v.w - hi_f(hp1));
}

#define MMA_BF16(d, a, b)                                                      \
    asm volatile(                                                              \
        "mma.sync.aligned.m16n8k16.row.col.f32.bf16.bf16.f32 "                 \
        "{%0,%1,%2,%3}, {%4,%5,%6,%7}, {%8,%9}, {%0,%1,%2,%3};"                \
        : "+f"((d)[0]), "+f"((d)[1]), "+f"((d)[2]), "+f"((d)[3])               \
        : "r"((a)[0]), "r"((a)[1]), "r"((a)[2]), "r"((a)[3]),                  \
          "r"((b)[0]), "r"((b)[1]))

// ---------------------------- small utility kernels -------------------------
__global__ void k_zero_small(unsigned* __restrict__ gmax, float* __restrict__ den,
                             float* __restrict__ pooled, int G) {
    int i = blockIdx.x * blockDim.x + threadIdx.x;
    if (i < G) { gmax[i] = 0u; den[i] = 0.f; }
    if (i < G * 256) pooled[i] = 0.f;
}

__global__ void k_zero_int(int* __restrict__ p, int n) {
    int i = blockIdx.x * blockDim.x + threadIdx.x;
    if (i < n) p[i] = 0;
}

// ---------------------------- CSR build -------------------------------------
__global__ void k_hist(const int* __restrict__ dst, int* __restrict__ deg, int E) {
    int i = blockIdx.x * blockDim.x + threadIdx.x;
    if (i < E) atomicAdd(&deg[__ldg(&dst[i])], 1);
}

// block of 256 threads scans 1024 elements -> exclusive offsets + block sum
__global__ void k_scan_block(const int* __restrict__ deg, int* __restrict__ off,
                             int* __restrict__ bsum, int n) {
    __shared__ int sh[256];
    int b = blockIdx.x, t = threadIdx.x;
    int i0 = b * 1024 + t * 4;
    int v[4];
#pragma unroll
    for (int j = 0; j < 4; j++) v[j] = (i0 + j < n) ? deg[i0 + j] : 0;
    int local = v[0] + v[1] + v[2] + v[3];
    sh[t] = local;
    __syncthreads();
#pragma unroll
    for (int o = 1; o < 256; o <<= 1) {
        int x = (t >= o) ? sh[t - o] : 0;
        __syncthreads();
        sh[t] += x;
        __syncthreads();
    }
    int run = sh[t] - local;   // exclusive prefix within block
#pragma unroll
    for (int j = 0; j < 4; j++) {
        if (i0 + j < n) off[i0 + j] = run;
        run += v[j];
    }
    if (t == 255) bsum[b] = sh[255];
}

__global__ void k_scan_top(int* __restrict__ bsum, int nb) {
    __shared__ int sh[512];
    int t = threadIdx.x;
    int v = (t < nb) ? bsum[t] : 0;
    sh[t] = v;
    __syncthreads();
#pragma unroll
    for (int o = 1; o < 512; o <<= 1) {
        int x = (t >= o) ? sh[t - o] : 0;
        __syncthreads();
        sh[t] += x;
        __syncthreads();
    }
    if (t < nb) bsum[t] = sh[t] - v;   // exclusive
}

__global__ void k_scan_add(int* __restrict__ off, const int* __restrict__ bsum,
                           int* __restrict__ cur, int n, int E) {
    int i = blockIdx.x * blockDim.x + threadIdx.x;
    if (i < n) {
        int o = off[i] + bsum[i >> 10];
        off[i] = o;
        cur[i] = o;
    }
    if (i == 0) off[n] = E;
}

__global__ void k_permute(const int* __restrict__ src, const int* __restrict__ dst,
                          int* __restrict__ cur, int* __restrict__ csr, int E) {
    int e = blockIdx.x * blockDim.x + threadIdx.x;
    if (e >= E) return;
    int d = __ldg(&dst[e]);
    int slot = atomicAdd(&cur[d], 1);
    csr[slot] = __ldg(&src[e]);
}

// ---------------------------- CSR gather ------------------------------------
// One warp per (node, 128-col slice). acc starts at x[node] (fused self term).
template <int F>
__global__ void k_gather(const float* __restrict__ x, const int* __restrict__ csr,
                         const int* __restrict__ off, float* __restrict__ outb,
                         int Nn) {
    constexpr int H = F / 128;
    int w = (blockIdx.x * blockDim.x + threadIdx.x) >> 5;
    int lane = threadIdx.x & 31;
    int node = w / H, half = w % H;
    if (node >= Nn) return;
    int i = __ldg(&off[node]);
    int end = __ldg(&off[node + 1]);
    size_t coff = (size_t)half * 128 + lane * 4;
    float4 acc = *(const float4*)(x + (size_t)node * F + coff);
    for (; i + 1 < end; i += 2) {
        int s0 = __ldg(&csr[i]);
        int s1 = __ldg(&csr[i + 1]);
        float4 v0 = __ldg((const float4*)(x + (size_t)s0 * F + coff));
        float4 v1 = __ldg((const float4*)(x + (size_t)s1 * F + coff));
        acc.x += v0.x + v1.x; acc.y += v0.y + v1.y;
        acc.z += v0.z + v1.z; acc.w += v0.w + v1.w;
    }
    if (i < end) {
        int s0 = __ldg(&csr[i]);
        float4 v0 = __ldg((const float4*)(x + (size_t)s0 * F + coff));
        acc.x += v0.x; acc.y += v0.y; acc.z += v0.z; acc.w += v0.w;
    }
    *(float4*)(outb + (size_t)node * F + coff) = acc;
}

// -------- weight transpose + bf16 hi/lo split + k-pair pack (per launch) ----
__global__ void k_wsplit(const float* __restrict__ W, uint32_t* __restrict__ Whp,
                         uint32_t* __restrict__ Wlp, int K, int N) {
    int i = blockIdx.x * blockDim.x + threadIdx.x;
    int K2 = K >> 1;
    if (i >= N * K2) return;
    int n = i / K2, k2 = i % K2;
    float v0 = W[(size_t)(2 * k2) * N + n];
    float v1 = W[(size_t)(2 * k2 + 1) * N + n];
    uint32_t hp = packbf(v0, v1);
    uint32_t lp = packbf(v0 - lo_f(hp), v1 - hi_f(hp));
    Whp[(size_t)n * K2 + k2] = hp;
    Wlp[(size_t)n * K2 + k2] = lp;
}

// ---------------------------- BF16x3 tensor-core GEMM ----------------------
template <bool RELU>
__global__ void __launch_bounds__(256)
k_gemm_bf(const float* __restrict__ A,
          const uint32_t* __restrict__ Whp, const uint32_t* __restrict__ Wlp,
          const float* __restrict__ bias, float* __restrict__ C,
          int M, int K, int N) {
    __shared__ uint32_t As_hi[128 * 20];
    __shared__ uint32_t As_lo[128 * 20];
    __shared__ uint32_t Bs_hi[128 * 20];
    __shared__ uint32_t Bs_lo[128 * 20];

    const int tid = threadIdx.x;
    const int lane = tid & 31;
    const int wid = tid >> 5;
    const int g = lane >> 2;
    const int t = lane & 3;
    const int mb = (wid >> 2) * 64;
    const int nb = (wid & 3) * 32;
    const int row0 = blockIdx.y * 128;
    const int col0 = blockIdx.x * 128;
    const int K2 = K >> 1;

    float acc[4][4][4];
#pragma unroll
    for (int i = 0; i < 4; i++)
#pragma unroll
        for (int j = 0; j < 4; j++)
#pragma unroll
            for (int r = 0; r < 4; r++) acc[i][j][r] = 0.f;

    for (int k0 = 0; k0 < K; k0 += 32) {
#pragma unroll
        for (int i = 0; i < 4; i++) {
            int s = tid + i * 256;
            int r = s >> 3, c4 = s & 7;
            int gr = row0 + r;
            float4 v = make_float4(0.f, 0.f, 0.f, 0.f);
            if (gr < M) v = *(const float4*)(A + (size_t)gr * K + k0 + c4 * 4);
            uint32_t hp0, hp1, lp0, lp1;
            split4(v, hp0, hp1, lp0, lp1);
            int o = r * 20 + c4 * 2;
            As_hi[o] = hp0; As_hi[o + 1] = hp1;
            As_lo[o] = lp0; As_lo[o + 1] = lp1;
        }
#pragma unroll
        for (int i = 0; i < 8; i++) {
            int s = tid + i * 256;
            int r = s >> 4, c2 = s & 15;
            size_t go = (size_t)(col0 + r) * K2 + (k0 >> 1) + c2;
            int o = r * 20 + c2;
            Bs_hi[o] = __ldg(&Whp[go]);
            Bs_lo[o] = __ldg(&Wlp[go]);
        }
        __syncthreads();

#pragma unroll
        for (int kk2 = 0; kk2 < 16; kk2 += 8) {
            uint32_t ah[4][4], al[4][4], bh[4][2], bl[4][2];
#pragma unroll
            for (int mf = 0; mf < 4; mf++) {
                int base = (mb + mf * 16 + g) * 20 + kk2 + t;
                ah[mf][0] = As_hi[base];
                ah[mf][1] = As_hi[base + 160];
                ah[mf][2] = As_hi[base + 4];
                ah[mf][3] = As_hi[base + 164];
                al[mf][0] = As_lo[base];
                al[mf][1] = As_lo[base + 160];
                al[mf][2] = As_lo[base + 4];
                al[mf][3] = As_lo[base + 164];
            }
#pragma unroll
            for (int nf = 0; nf < 4; nf++) {
                int base = (nb + nf * 8 + g) * 20 + kk2 + t;
                bh[nf][0] = Bs_hi[base];
                bh[nf][1] = Bs_hi[base + 4];
                bl[nf][0] = Bs_lo[base];
                bl[nf][1] = Bs_lo[base + 4];
            }
#pragma unroll
            for (int mf = 0; mf < 4; mf++)
#pragma unroll
                for (int nf = 0; nf < 4; nf++) {
                    MMA_BF16(acc[mf][nf], al[mf], bh[nf]);
                    MMA_BF16(acc[mf][nf], ah[mf], bl[nf]);
                    MMA_BF16(acc[mf][nf], ah[mf], bh[nf]);
                }
        }
        __syncthreads();
    }

#pragma unroll
    for (int mf = 0; mf < 4; mf++) {
        int r0 = row0 + mb + mf * 16 + g;
        int r1 = r0 + 8;
#pragma unroll
        for (int nf = 0; nf < 4; nf++) {
            int c = col0 + nb + nf * 8 + 2 * t;
            float bx = __ldg(&bias[c]);
            float by = __ldg(&bias[c + 1]);
            float v0 = acc[mf][nf][0] + bx;
            float v1 = acc[mf][nf][1] + by;
            float v2 = acc[mf][nf][2] + bx;
            float v3 = acc[mf][nf][3] + by;
            if (RELU) {
                v0 = fmaxf(v0, 0.f); v1 = fmaxf(v1, 0.f);
                v2 = fmaxf(v2, 0.f); v3 = fmaxf(v3, 0.f);
            }
            if (r0 < M) { float2 o = {v0, v1}; *(float2*)(C + (size_t)r0 * N + c) = o; }
            if (r1 < M) { float2 o = {v2, v3}; *(float2*)(C + (size_t)r1 * N + c) = o; }
        }
    }
}

// ---------------------------- LayerNorm + ReLU (in place, 256 cols) --------
__global__ void k_ln(float* __restrict__ h, const float* __restrict__ gamma,
                     const float* __restrict__ beta, int M) {
    int row = blockIdx.x * 8 + (threadIdx.x >> 5);
    int lane = threadIdx.x & 31;
    if (row >= M) return;
    float4* p = (float4*)(h + (size_t)row * 256);
    float4 v0 = p[lane];
    float4 v1 = p[lane + 32];
    float s = v0.x + v0.y + v0.z + v0.w + v1.x + v1.y + v1.z + v1.w;
    float ss = v0.x * v0.x + v0.y * v0.y + v0.z * v0.z + v0.w * v0.w
             + v1.x * v1.x + v1.y * v1.y + v1.z * v1.z + v1.w * v1.w;
#pragma unroll
    for (int off = 16; off > 0; off >>= 1) {
        s  += __shfl_xor_sync(0xffffffffu, s, off);
        ss += __shfl_xor_sync(0xffffffffu, ss, off);
    }
    float mean = s * (1.f / 256.f);
    float var  = ss * (1.f / 256.f) - mean * mean;
    float inv  = rsqrtf(var + 1e-5f);
    const float4* g4 = (const float4*)gamma;
    const float4* b4 = (const float4*)beta;
    float4 g0 = __ldg(&g4[lane]),      b0 = __ldg(&b4[lane]);
    float4 g1 = __ldg(&g4[lane + 32]), b1 = __ldg(&b4[lane + 32]);
    float4 o0, o1;
    o0.x = fmaxf((v0.x - mean) * inv * g0.x + b0.x, 0.f);
    o0.y = fmaxf((v0.y - mean) * inv * g0.y + b0.y, 0.f);
    o0.z = fmaxf((v0.z - mean) * inv * g0.z + b0.z, 0.f);
    o0.w = fmaxf((v0.w - mean) * inv * g0.w + b0.w, 0.f);
    o1.x = fmaxf((v1.x - mean) * inv * g1.x + b1.x, 0.f);
    o1.y = fmaxf((v1.y - mean) * inv * g1.y + b1.y, 0.f);
    o1.z = fmaxf((v1.z - mean) * inv * g1.z + b1.z, 0.f);
    o1.w = fmaxf((v1.w - mean) * inv * g1.w + b1.w, 0.f);
    p[lane] = o0;
    p[lane + 32] = o1;
}

// ---------------------------- gate second layer (128 -> 1) -----------------
__global__ void k_gatedot(const float* __restrict__ t, const float* __restrict__ w2,
                          const float* __restrict__ b2, float* __restrict__ gate, int M) {
    int row = blockIdx.x * 8 + (threadIdx.x >> 5);
    int lane = threadIdx.x & 31;
    if (row >= M) return;
    float4 v = __ldg(&((const float4*)(t + (size_t)row * 128))[lane]);
    float4 w = __ldg(&((const float4*)w2)[lane]);
    float s = v.x * w.x + v.y * w.y + v.z * w.z + v.w * w.w;
#pragma unroll
    for (int off = 16; off > 0; off >>= 1)
        s += __shfl_xor_sync(0xffffffffu, s, off);
    if (lane == 0) gate[row] = s + __ldg(&b2[0]);
}

// ---------------------------- segment softmax + pool ------------------------
__device__ __forceinline__ unsigned enc_ord(float f) {
    unsigned u = __float_as_uint(f);
    return (u & 0x80000000u) ? ~u : (u | 0x80000000u);
}
__device__ __forceinline__ float dec_ord(unsigned u) {
    unsigned v = (u & 0x80000000u) ? (u & 0x7fffffffu) : ~u;
    return __uint_as_float(v);
}

__device__ __forceinline__ void red_add_v4(float* addr, float4 v) {
    asm volatile("red.global.add.v4.f32 [%0], {%1,%2,%3,%4};"
                 :: "l"(addr), "f"(v.x), "f"(v.y), "f"(v.z), "f"(v.w)
                 : "memory");
}

__global__ void k_segmax(const float* __restrict__ gate, const int* __restrict__ batch,
                         unsigned* __restrict__ gmax, int Nn) {
    int i = blockIdx.x * blockDim.x + threadIdx.x;
    if (i >= Nn) return;
    atomicMax(&gmax[__ldg(&batch[i])], enc_ord(__ldg(&gate[i])));
}

__global__ void k_segexp(const float* __restrict__ gate, const int* __restrict__ batch,
                         const unsigned* __restrict__ gmax, float* __restrict__ ex,
                         float* __restrict__ den, int Nn) {
    int i = blockIdx.x * blockDim.x + threadIdx.x;
    if (i >= Nn) return;
    int b = __ldg(&batch[i]);
    float e = expf(__ldg(&gate[i]) - dec_ord(gmax[b]));
    ex[i] = e;
    atomicAdd(&den[b], e);
}

__global__ void k_pool(const float* __restrict__ h, const int* __restrict__ batch,
                       const float* __restrict__ ex, const float* __restrict__ den,
                       float* __restrict__ pooled, int Nn) {
    int gid = blockIdx.x * blockDim.x + threadIdx.x;
    int i = gid >> 6;
    int q = gid & 63;
    if (i >= Nn) return;
    int b = __ldg(&batch[i]);
    float alpha = __ldg(&ex[i]) / __ldg(&den[b]);
    float4 v = __ldg(&((const float4*)(h + (size_t)i * 256))[q]);
    v.x *= alpha; v.y *= alpha; v.z *= alpha; v.w *= alpha;
    red_add_v4(pooled + (size_t)b * 256 + q * 4, v);
}

// ---------------------------- classifier ------------------------------------
__global__ void __launch_bounds__(128)
k_cls(const float* __restrict__ pooled, const float* __restrict__ w1,
      const float* __restrict__ b1, const float* __restrict__ w2,
      const float* __restrict__ b2, float* __restrict__ out) {
    __shared__ float sp[256];
    __shared__ float r0s[4], r1s[4];
    int g = blockIdx.x;
    int tid = threadIdx.x;
    sp[tid] = pooled[(size_t)g * 256 + tid];
    sp[tid + 128] = pooled[(size_t)g * 256 + tid + 128];
    __syncthreads();
    float acc = __ldg(&b1[tid]);
#pragma unroll 8
    for (int k = 0; k < 256; k++) acc += sp[k] * __ldg(&w1[k * 128 + tid]);
    float q = fmaxf(acc, 0.f);
    float o0 = q * __ldg(&w2[tid * 2 + 0]);
    float o1 = q * __ldg(&w2[tid * 2 + 1]);
#pragma unroll
    for (int off = 16; off > 0; off >>= 1) {
        o0 += __shfl_xor_sync(0xffffffffu, o0, off);
        o1 += __shfl_xor_sync(0xffffffffu, o1, off);
    }
    int wid = tid >> 5, lane = tid & 31;
    if (lane == 0) { r0s[wid] = o0; r1s[wid] = o1; }
    __syncthreads();
    if (tid == 0) {
        float s0 = r0s[0] + r0s[1] + r0s[2] + r0s[3];
        float s1 = r1s[0] + r1s[1] + r1s[2] + r1s[3];
        out[g * 2 + 0] = s0 + __ldg(&b2[0]);
        out[g * 2 + 1] = s1 + __ldg(&b2[1]);
    }
}

// ---------------------------------------------------------------------------
extern "C" void kernel_launch(void* const* d_in, const int* in_sizes, int n_in,
                              void* d_out, int out_size) {
    const float* x       = (const float*)d_in[0];
    const int*   ei      = (const int*)d_in[1];
    const int*   batch   = (const int*)d_in[2];
    const float* w1_0    = (const float*)d_in[4];
    const float* b1_0    = (const float*)d_in[5];
    const float* w2_0    = (const float*)d_in[6];
    const float* b2_0    = (const float*)d_in[7];
    const float* ln_g0   = (const float*)d_in[8];
    const float* ln_b0   = (const float*)d_in[9];
    const float* w1_1    = (const float*)d_in[10];
    const float* b1_1    = (const float*)d_in[11];
    const float* w2_1    = (const float*)d_in[12];
    const float* b2_1    = (const float*)d_in[13];
    const float* ln_g1   = (const float*)d_in[14];
    const float* ln_b1   = (const float*)d_in[15];
    const float* gate_w1 = (const float*)d_in[16];
    const float* gate_b1 = (const float*)d_in[17];
    const float* gate_w2 = (const float*)d_in[18];
    const float* gate_b2 = (const float*)d_in[19];
    const float* cls_w1  = (const float*)d_in[20];
    const float* cls_b1  = (const float*)d_in[21];
    const float* cls_w2  = (const float*)d_in[22];
    const float* cls_b2  = (const float*)d_in[23];
    float* out = (float*)d_out;

    const int N = in_sizes[0] / 128;
    const int E = in_sizes[1] / 2;
    const int G = out_size / 2;
    const int* src = ei;
    const int* dst = ei + E;

    float *bufA, *bufB, *bufC, *gate, *ex, *den, *pooled;
    unsigned* gmax;
    uint32_t* wt;
    int *deg, *off, *cur, *csr, *bsum;
    cudaGetSymbolAddress((void**)&bufA, g_bufA);
    cudaGetSymbolAddress((void**)&bufB, g_bufB);
    cudaGetSymbolAddress((void**)&bufC, g_bufC);
    cudaGetSymbolAddress((void**)&gate, g_gate);
    cudaGetSymbolAddress((void**)&ex, g_exp);
    cudaGetSymbolAddress((void**)&gmax, g_gmax);
    cudaGetSymbolAddress((void**)&den, g_den);
    cudaGetSymbolAddress((void**)&pooled, g_pooled);
    cudaGetSymbolAddress((void**)&wt, g_wt);
    cudaGetSymbolAddress((void**)&deg, g_deg);
    cudaGetSymbolAddress((void**)&off, g_off);
    cudaGetSymbolAddress((void**)&cur, g_cur);
    cudaGetSymbolAddress((void**)&csr, g_csr);
    cudaGetSymbolAddress((void**)&bsum, g_bsum);

    const size_t WS = 256 * 128;
    uint32_t* w10h = wt + 0 * 2 * WS; uint32_t* w10l = w10h + WS;
    uint32_t* w20h = wt + 1 * 2 * WS; uint32_t* w20l = w20h + WS;
    uint32_t* w11h = wt + 2 * 2 * WS; uint32_t* w11l = w11h + WS;
    uint32_t* w21h = wt + 3 * 2 * WS; uint32_t* w21l = w21h + WS;
    uint32_t* gw1h = wt + 4 * 2 * WS; uint32_t* gw1l = gw1h + WS;

    dim3 g256(2, cdiv(N, 128));
    dim3 g128(1, cdiv(N, 128));
    const int nb = cdiv(N, 1024);

    // ---- CSR build (once; reused by both layers) ----
    k_zero_int<<<cdiv(N, 256), 256>>>(deg, N);
    k_hist<<<cdiv(E, 256), 256>>>(dst, deg, E);
    k_scan_block<<<nb, 256>>>(deg, off, bsum, N);
    k_scan_top<<<1, 512>>>(bsum, nb);
    k_scan_add<<<cdiv(N, 256), 256>>>(off, bsum, cur, N, E);
    k_permute<<<cdiv(E, 256), 256>>>(src, dst, cur, csr, E);

    // ---- weight preprocessing ----
    k_wsplit<<<cdiv(256 * 64, 256), 256>>>(w1_0, w10h, w10l, 128, 256);
    k_wsplit<<<cdiv(256 * 128, 256), 256>>>(w2_0, w20h, w20l, 256, 256);
    k_wsplit<<<cdiv(256 * 128, 256), 256>>>(w1_1, w11h, w11l, 256, 256);
    k_wsplit<<<cdiv(256 * 128, 256), 256>>>(w2_1, w21h, w21l, 256, 256);
    k_wsplit<<<cdiv(128 * 128, 256), 256>>>(gate_w1, gw1h, gw1l, 256, 128);

    // ---- layer 0 ----
    k_gather<128><<<cdiv(N * 32, 256), 256>>>(x, csr, off, bufA, N);
    k_gemm_bf<true><<<g256, 256>>>(bufA, w10h, w10l, b1_0, bufB, N, 128, 256);
    k_gemm_bf<false><<<g256, 256>>>(bufB, w20h, w20l, b2_0, bufC, N, 256, 256);
    k_ln<<<cdiv(N, 8), 256>>>(bufC, ln_g0, ln_b0, N);

    // ---- layer 1 ----
    k_gather<256><<<cdiv(N * 64, 256), 256>>>(bufC, csr, off, bufA, N);
    k_gemm_bf<true><<<g256, 256>>>(bufA, w11h, w11l, b1_1, bufB, N, 256, 256);
    k_gemm_bf<false><<<g256, 256>>>(bufB, w21h, w21l, b2_1, bufA, N, 256, 256);
    k_ln<<<cdiv(N, 8), 256>>>(bufA, ln_g1, ln_b1, N);                 // bufA = h1

    // ---- gate ----
    k_gemm_bf<true><<<g128, 256>>>(bufA, gw1h, gw1l, gate_b1, bufB, N, 256, 128);
    k_gatedot<<<cdiv(N, 8), 256>>>(bufB, gate_w2, gate_b2, gate, N);

    // ---- segment softmax + pooled ----
    k_zero_small<<<cdiv(G * 256, 256), 256>>>(gmax, den, pooled, G);
    k_segmax<<<cdiv(N, 256), 256>>>(gate, batch, gmax, N);
    k_segexp<<<cdiv(N, 256), 256>>>(gate, batch, gmax, ex, den, N);
    k_pool<<<cdiv(N * 64, 256), 256>>>(bufA, batch, ex, den, pooled, N);

    // ---- classifier ----
    k_cls<<<G, 128>>>(pooled, cls_w1, cls_b1, cls_w2, cls_b2, out);
}